// round 4
// baseline (speedup 1.0000x reference)
#include <cuda_runtime.h>
#include <math.h>

// ResidueGCN: 3-layer GraphSAGE (pool aggregator)
// Inputs (metadata order):
//  0:h[10000,960] 1:src[160000] 2:dst[160000]
//  3:Wp0[960,960] 4:bp0[960] 5:Ws0[960,512] 6:Wn0[960,512] 7:b0[512]
//  8:Wp1[512,512] 9:bp1[512] 10:Ws1[512,512] 11:Wn1[512,512] 12:b1[512]
// 13:Wp2[512,512] 14:bp2[512] 15:Ws2[512,1] 16:Wn2[512,1] 17:b2[1]
// out: [10000] float32

#define N_NODES 10000
#define N_EDGES 160000

// Scratch (device globals; allocation is forbidden)
__device__ float g_m[N_NODES * 960];      // pooled transform (max feature dim)
__device__ float g_neigh[N_NODES * 960];  // segment-max result
__device__ float g_x0[N_NODES * 512];     // layer0 output
__device__ float g_x1[N_NODES * 512];     // layer1 output

// ---------------------------------------------------------------------------
// Tiled SGEMM: C[M,N] = act( A1@B1 (+ A2@B2 if DUAL) + bias )
// BM=128, BN=64, BK=16, 256 threads, 8x4 microtile per thread.
// Software-pipelined: next K-tile staged in registers during compute.
// Requires: K % 16 == 0, N % 64 == 0 (true for 960/512). M edge guarded.
// ---------------------------------------------------------------------------
template <bool RELU, bool DUAL>
__global__ __launch_bounds__(256)
void gemm_kernel(const float* __restrict__ A1, const float* __restrict__ B1,
                 const float* __restrict__ A2, const float* __restrict__ B2,
                 const float* __restrict__ bias, float* __restrict__ C,
                 int M, int N, int K) {
    const int BM = 128, BN = 64, BK = 16;
    __shared__ float As[BK][BM + 4];
    __shared__ float Bs[BK][BN];

    const int tid = threadIdx.x;
    const int tx = tid & 15;   // N direction (16 * 4 = 64)
    const int ty = tid >> 4;   // M direction (16 * 8 = 128)
    const int row0 = blockIdx.y * BM;
    const int col0 = blockIdx.x * BN;

    // A-load geometry: 2 float4 per thread (512 float4 = 128 rows x 4 quads)
    const int a_m0 = tid >> 2;              // row within tile, iter 0 (0..63)
    const int a_m1 = (tid + 256) >> 2;      // row within tile, iter 1 (64..127)
    const int a_kq = tid & 3;               // K-quad
    // B-load geometry: 1 float4 per thread
    const int b_n4 = tid & 15;
    const int b_k  = tid >> 4;

    float acc[8][4];
#pragma unroll
    for (int i = 0; i < 8; i++)
#pragma unroll
        for (int j = 0; j < 4; j++) acc[i][j] = 0.0f;

    const int npass = DUAL ? 2 : 1;
    for (int pass = 0; pass < npass; ++pass) {
        const float* __restrict__ A = (DUAL && pass) ? A2 : A1;
        const float* __restrict__ B = (DUAL && pass) ? B2 : B1;

        // Prologue: fetch tile 0 into registers
        float4 ra0 = make_float4(0.f, 0.f, 0.f, 0.f);
        float4 ra1 = make_float4(0.f, 0.f, 0.f, 0.f);
        float4 rb;
        if (row0 + a_m0 < M)
            ra0 = *(const float4*)(A + (size_t)(row0 + a_m0) * K + a_kq * 4);
        if (row0 + a_m1 < M)
            ra1 = *(const float4*)(A + (size_t)(row0 + a_m1) * K + a_kq * 4);
        rb = *(const float4*)(B + (size_t)b_k * N + col0 + b_n4 * 4);

        for (int k0 = 0; k0 < K; k0 += BK) {
            // Commit staged registers to shared
            As[a_kq * 4 + 0][a_m0] = ra0.x;
            As[a_kq * 4 + 1][a_m0] = ra0.y;
            As[a_kq * 4 + 2][a_m0] = ra0.z;
            As[a_kq * 4 + 3][a_m0] = ra0.w;
            As[a_kq * 4 + 0][a_m1] = ra1.x;
            As[a_kq * 4 + 1][a_m1] = ra1.y;
            As[a_kq * 4 + 2][a_m1] = ra1.z;
            As[a_kq * 4 + 3][a_m1] = ra1.w;
            *(float4*)&Bs[b_k][b_n4 * 4] = rb;
            __syncthreads();

            // Stage next tile (overlaps with FMA work below)
            int kn = k0 + BK;
            if (kn < K) {
                if (row0 + a_m0 < M)
                    ra0 = *(const float4*)(A + (size_t)(row0 + a_m0) * K + kn + a_kq * 4);
                if (row0 + a_m1 < M)
                    ra1 = *(const float4*)(A + (size_t)(row0 + a_m1) * K + kn + a_kq * 4);
                rb = *(const float4*)(B + (size_t)(kn + b_k) * N + col0 + b_n4 * 4);
            }

#pragma unroll
            for (int k = 0; k < BK; k++) {
                float a[8], b[4];
#pragma unroll
                for (int i = 0; i < 8; i++) a[i] = As[k][ty * 8 + i];
#pragma unroll
                for (int j = 0; j < 4; j++) b[j] = Bs[k][tx * 4 + j];
#pragma unroll
                for (int i = 0; i < 8; i++)
#pragma unroll
                    for (int j = 0; j < 4; j++) acc[i][j] = fmaf(a[i], b[j], acc[i][j]);
            }
            __syncthreads();
        }
    }

    // Epilogue
#pragma unroll
    for (int i = 0; i < 8; i++) {
        int row = row0 + ty * 8 + i;
        if (row < M) {
#pragma unroll
            for (int j = 0; j < 4; j++) {
                int col = col0 + tx * 4 + j;
                float v = acc[i][j] + bias[col];
                if (RELU) v = fmaxf(v, 0.0f);
                C[(size_t)row * N + col] = v;
            }
        }
    }
}

// Zero-init first n floats (bit pattern 0 == 0.0f, valid floor for relu'd max)
__global__ void zero_kernel(float* __restrict__ p, size_t n) {
    size_t i = (size_t)blockIdx.x * blockDim.x + threadIdx.x;
    size_t stride = (size_t)gridDim.x * blockDim.x;
    for (; i < n; i += stride) p[i] = 0.0f;
}

// Edge segment-max: neigh[dst] = max(neigh[dst], m[src]) elementwise.
// m >= 0 (relu), so int-bitpattern atomicMax == float max.
// One warp per edge, 8 warps (8 edges) per block.
// Gather side vectorized: float4 loads (d % 128 == 0 for d in {512, 960}).
__global__ __launch_bounds__(256)
void edge_max_kernel(const int* __restrict__ src,
                     const int* __restrict__ dst,
                     const float* __restrict__ m,
                     float* __restrict__ neigh, int d) {
    int e = blockIdx.x * 8 + (threadIdx.x >> 5);
    if (e >= N_EDGES) return;
    int lane = threadIdx.x & 31;
    int s = src[e];
    int t = dst[e];
    const float4* __restrict__ mrow = (const float4*)(m + (size_t)s * d);
    int* __restrict__ nrow = (int*)(neigh + (size_t)t * d);
    int d4 = d >> 2;
    for (int q = lane; q < d4; q += 32) {
        float4 v = mrow[q];
        int f = q * 4;
        atomicMax(nrow + f + 0, __float_as_int(v.x));
        atomicMax(nrow + f + 1, __float_as_int(v.y));
        atomicMax(nrow + f + 2, __float_as_int(v.z));
        atomicMax(nrow + f + 3, __float_as_int(v.w));
    }
}

// Final layer (d_out = 1): out[i] = sigmoid(dot(x[i],Ws2) + dot(neigh[i],Wn2) + b2)
// One warp per node.
__global__ __launch_bounds__(256)
void out_kernel(const float* __restrict__ x, const float* __restrict__ neigh,
                const float* __restrict__ Ws, const float* __restrict__ Wn,
                const float* __restrict__ b, float* __restrict__ out) {
    int warp = (blockIdx.x * blockDim.x + threadIdx.x) >> 5;
    int lane = threadIdx.x & 31;
    if (warp >= N_NODES) return;
    const float* __restrict__ xr = x + (size_t)warp * 512;
    const float* __restrict__ nr = neigh + (size_t)warp * 512;
    float s = 0.0f;
#pragma unroll 4
    for (int f = lane; f < 512; f += 32)
        s = fmaf(xr[f], Ws[f], fmaf(nr[f], Wn[f], s));
#pragma unroll
    for (int o = 16; o; o >>= 1) s += __shfl_xor_sync(0xFFFFFFFFu, s, o);
    if (lane == 0) out[warp] = 1.0f / (1.0f + expf(-(s + b[0])));
}

extern "C" void kernel_launch(void* const* d_in, const int* in_sizes, int n_in,
                              void* d_out, int out_size) {
    const float* h   = (const float*)d_in[0];
    const int*   src = (const int*)d_in[1];
    const int*   dst = (const int*)d_in[2];
    const float* Wp0 = (const float*)d_in[3];
    const float* bp0 = (const float*)d_in[4];
    const float* Ws0 = (const float*)d_in[5];
    const float* Wn0 = (const float*)d_in[6];
    const float* b0  = (const float*)d_in[7];
    const float* Wp1 = (const float*)d_in[8];
    const float* bp1 = (const float*)d_in[9];
    const float* Ws1 = (const float*)d_in[10];
    const float* Wn1 = (const float*)d_in[11];
    const float* b1  = (const float*)d_in[12];
    const float* Wp2 = (const float*)d_in[13];
    const float* bp2 = (const float*)d_in[14];
    const float* Ws2 = (const float*)d_in[15];
    const float* Wn2 = (const float*)d_in[16];
    const float* b2  = (const float*)d_in[17];
    float* out = (float*)d_out;

    float *m_buf, *neigh_buf, *x0_buf, *x1_buf;
    cudaGetSymbolAddress((void**)&m_buf, g_m);
    cudaGetSymbolAddress((void**)&neigh_buf, g_neigh);
    cudaGetSymbolAddress((void**)&x0_buf, g_x0);
    cudaGetSymbolAddress((void**)&x1_buf, g_x1);

    const int M = N_NODES;
    const int mtiles = (M + 127) / 128;
    const int eblocks = (N_EDGES + 7) / 8;

    // ---------------- Layer 0 (960 -> 512) ----------------
    // m = relu(h @ Wp0 + bp0)   [10000, 960]
    gemm_kernel<true, false><<<dim3(960 / 64, mtiles), 256>>>(
        h, Wp0, nullptr, nullptr, bp0, m_buf, M, 960, 960);
    zero_kernel<<<512, 256>>>(neigh_buf, (size_t)N_NODES * 960);
    edge_max_kernel<<<eblocks, 256>>>(src, dst, m_buf, neigh_buf, 960);
    // x0 = relu(h @ Ws0 + neigh @ Wn0 + b0)   [10000, 512]
    gemm_kernel<true, true><<<dim3(512 / 64, mtiles), 256>>>(
        h, Ws0, neigh_buf, Wn0, b0, x0_buf, M, 512, 960);

    // ---------------- Layer 1 (512 -> 512) ----------------
    gemm_kernel<true, false><<<dim3(512 / 64, mtiles), 256>>>(
        x0_buf, Wp1, nullptr, nullptr, bp1, m_buf, M, 512, 512);
    zero_kernel<<<512, 256>>>(neigh_buf, (size_t)N_NODES * 512);
    edge_max_kernel<<<eblocks, 256>>>(src, dst, m_buf, neigh_buf, 512);
    gemm_kernel<true, true><<<dim3(512 / 64, mtiles), 256>>>(
        x0_buf, Ws1, neigh_buf, Wn1, b1, x1_buf, M, 512, 512);

    // ---------------- Layer 2 (512 -> 1, sigmoid) ----------------
    gemm_kernel<true, false><<<dim3(512 / 64, mtiles), 256>>>(
        x1_buf, Wp2, nullptr, nullptr, bp2, m_buf, M, 512, 512);
    zero_kernel<<<512, 256>>>(neigh_buf, (size_t)N_NODES * 512);
    edge_max_kernel<<<eblocks, 256>>>(src, dst, m_buf, neigh_buf, 512);
    out_kernel<<<(N_NODES * 32 + 255) / 256, 256>>>(
        x1_buf, neigh_buf, Ws2, Wn2, b2, out);
}

// round 5
// speedup vs baseline: 1.0737x; 1.0737x over previous
#include <cuda_runtime.h>
#include <math.h>

// ResidueGCN: 3-layer GraphSAGE (pool aggregator)
// GEMMs on tensor cores via 3xTF32 mma.sync (fp32-accurate split).

#define N_NODES 10000
#define N_EDGES 160000

// Scratch (device globals; allocation is forbidden)
__device__ float g_m[N_NODES * 960];
__device__ float g_neigh[N_NODES * 960];
__device__ float g_x0[N_NODES * 512];
__device__ float g_x1[N_NODES * 512];

__device__ __forceinline__ unsigned f2tf(float x) {
    unsigned r;
    asm("cvt.rna.tf32.f32 %0, %1;" : "=r"(r) : "f"(x));
    return r;
}

__device__ __forceinline__ void mma8(float* d, const unsigned* a, const unsigned* b) {
    asm volatile(
        "mma.sync.aligned.m16n8k8.row.col.f32.tf32.tf32.f32 "
        "{%0,%1,%2,%3}, {%4,%5,%6,%7}, {%8,%9}, {%0,%1,%2,%3};"
        : "+f"(d[0]), "+f"(d[1]), "+f"(d[2]), "+f"(d[3])
        : "r"(a[0]), "r"(a[1]), "r"(a[2]), "r"(a[3]), "r"(b[0]), "r"(b[1]));
}

// ---------------------------------------------------------------------------
// Tensor-core GEMM: C[M,N] = act( A1@B1 (+ A2@B2 if DUAL) + bias )
// BM=128, BN=64, BK=16, 256 threads (8 warps: 2 over M x 4 over N).
// Warp tile m64 x n16 (4 m16-frags x 2 n8-frags), 3xTF32 split for fp32 accuracy.
// A staged hi/lo in smem [m][k] stride 20; B staged hi/lo [k][n] stride 72.
// Both layouts verified bank-conflict-free for the m16n8k8 fragment patterns.
// Requires K % 16 == 0, N % 64 == 0 (holds: 960/512). M edge guarded.
// ---------------------------------------------------------------------------
template <bool RELU, bool DUAL>
__global__ __launch_bounds__(256, 2)
void gemm_tc(const float* __restrict__ A1, const float* __restrict__ B1,
             const float* __restrict__ A2, const float* __restrict__ B2,
             const float* __restrict__ bias, float* __restrict__ C,
             int M, int N, int K) {
    const int BM = 128, BN = 64, BK = 16;
    const int ASTR = BK + 4;   // 20 floats
    const int BSTR = BN + 8;   // 72 floats
    __shared__ unsigned sAh[BM * ASTR], sAl[BM * ASTR];
    __shared__ unsigned sBh[BK * BSTR], sBl[BK * BSTR];

    const int tid = threadIdx.x;
    const int lane = tid & 31, wid = tid >> 5;
    const int warp_m = wid & 1;        // 0..1 (64 rows each)
    const int warp_n = wid >> 1;       // 0..3 (16 cols each)
    const int row0 = blockIdx.y * BM;
    const int col0 = blockIdx.x * BN;
    const int g = lane >> 2;           // groupID 0..7
    const int tg = lane & 3;           // threadID_in_group 0..3

    // Staging geometry: A = 2 float4/thread, B = 1 float4/thread
    const int a_m0 = tid >> 2;         // 0..63
    const int a_m1 = a_m0 + 64;        // 64..127
    const int a_kq = (tid & 3) * 4;    // 0,4,8,12
    const int b_k = tid >> 4;          // 0..15
    const int b_n = (tid & 15) * 4;    // 0..60

    float acc[4][2][4];
#pragma unroll
    for (int i = 0; i < 4; i++)
#pragma unroll
        for (int j = 0; j < 2; j++)
#pragma unroll
            for (int r = 0; r < 4; r++) acc[i][j][r] = 0.0f;

    const int npass = DUAL ? 2 : 1;
    for (int pass = 0; pass < npass; ++pass) {
        const float* __restrict__ A = (DUAL && pass) ? A2 : A1;
        const float* __restrict__ B = (DUAL && pass) ? B2 : B1;

        float4 ra0 = make_float4(0.f, 0.f, 0.f, 0.f);
        float4 ra1 = make_float4(0.f, 0.f, 0.f, 0.f);
        float4 rb;
        if (row0 + a_m0 < M)
            ra0 = *(const float4*)(A + (size_t)(row0 + a_m0) * K + a_kq);
        if (row0 + a_m1 < M)
            ra1 = *(const float4*)(A + (size_t)(row0 + a_m1) * K + a_kq);
        rb = *(const float4*)(B + (size_t)b_k * N + col0 + b_n);

        for (int k0 = 0; k0 < K; k0 += BK) {
            // Convert staged tile to tf32 hi/lo and commit to smem (STS.128)
            {
                float4 v = ra0;
                unsigned h0 = f2tf(v.x), h1 = f2tf(v.y), h2 = f2tf(v.z), h3 = f2tf(v.w);
                unsigned l0 = f2tf(v.x - __uint_as_float(h0));
                unsigned l1 = f2tf(v.y - __uint_as_float(h1));
                unsigned l2 = f2tf(v.z - __uint_as_float(h2));
                unsigned l3 = f2tf(v.w - __uint_as_float(h3));
                *(uint4*)(sAh + a_m0 * ASTR + a_kq) = make_uint4(h0, h1, h2, h3);
                *(uint4*)(sAl + a_m0 * ASTR + a_kq) = make_uint4(l0, l1, l2, l3);
            }
            {
                float4 v = ra1;
                unsigned h0 = f2tf(v.x), h1 = f2tf(v.y), h2 = f2tf(v.z), h3 = f2tf(v.w);
                unsigned l0 = f2tf(v.x - __uint_as_float(h0));
                unsigned l1 = f2tf(v.y - __uint_as_float(h1));
                unsigned l2 = f2tf(v.z - __uint_as_float(h2));
                unsigned l3 = f2tf(v.w - __uint_as_float(h3));
                *(uint4*)(sAh + a_m1 * ASTR + a_kq) = make_uint4(h0, h1, h2, h3);
                *(uint4*)(sAl + a_m1 * ASTR + a_kq) = make_uint4(l0, l1, l2, l3);
            }
            {
                float4 v = rb;
                unsigned h0 = f2tf(v.x), h1 = f2tf(v.y), h2 = f2tf(v.z), h3 = f2tf(v.w);
                unsigned l0 = f2tf(v.x - __uint_as_float(h0));
                unsigned l1 = f2tf(v.y - __uint_as_float(h1));
                unsigned l2 = f2tf(v.z - __uint_as_float(h2));
                unsigned l3 = f2tf(v.w - __uint_as_float(h3));
                *(uint4*)(sBh + b_k * BSTR + b_n) = make_uint4(h0, h1, h2, h3);
                *(uint4*)(sBl + b_k * BSTR + b_n) = make_uint4(l0, l1, l2, l3);
            }
            __syncthreads();

            // Stage next tile (overlaps with MMA work below)
            int kn = k0 + BK;
            if (kn < K) {
                ra0 = make_float4(0.f, 0.f, 0.f, 0.f);
                ra1 = make_float4(0.f, 0.f, 0.f, 0.f);
                if (row0 + a_m0 < M)
                    ra0 = *(const float4*)(A + (size_t)(row0 + a_m0) * K + kn + a_kq);
                if (row0 + a_m1 < M)
                    ra1 = *(const float4*)(A + (size_t)(row0 + a_m1) * K + kn + a_kq);
                rb = *(const float4*)(B + (size_t)(kn + b_k) * N + col0 + b_n);
            }

#pragma unroll
            for (int ks = 0; ks < 2; ks++) {
                const int kk = ks * 8;
                unsigned ah[4][4], al[4][4], bh[2][2], bl[2][2];
#pragma unroll
                for (int fm = 0; fm < 4; fm++) {
                    int r = warp_m * 64 + fm * 16 + g;
                    int i0 = r * ASTR + kk + tg;
                    int i1 = (r + 8) * ASTR + kk + tg;
                    ah[fm][0] = sAh[i0];
                    ah[fm][1] = sAh[i1];
                    ah[fm][2] = sAh[i0 + 4];
                    ah[fm][3] = sAh[i1 + 4];
                    al[fm][0] = sAl[i0];
                    al[fm][1] = sAl[i1];
                    al[fm][2] = sAl[i0 + 4];
                    al[fm][3] = sAl[i1 + 4];
                }
#pragma unroll
                for (int fn = 0; fn < 2; fn++) {
                    int n = warp_n * 16 + fn * 8 + g;
                    int i0 = (kk + tg) * BSTR + n;
                    bh[fn][0] = sBh[i0];
                    bh[fn][1] = sBh[i0 + 4 * BSTR];
                    bl[fn][0] = sBl[i0];
                    bl[fn][1] = sBl[i0 + 4 * BSTR];
                }
#pragma unroll
                for (int fm = 0; fm < 4; fm++)
#pragma unroll
                    for (int fn = 0; fn < 2; fn++) {
                        mma8(acc[fm][fn], ah[fm], bh[fn]);
                        mma8(acc[fm][fn], al[fm], bh[fn]);
                        mma8(acc[fm][fn], ah[fm], bl[fn]);
                    }
            }
            __syncthreads();
        }
    }

    // Epilogue: c0,c1 at (row, col+{0,1}); c2,c3 at (row+8, col+{0,1})
#pragma unroll
    for (int fm = 0; fm < 4; fm++) {
        int row = row0 + warp_m * 64 + fm * 16 + g;
#pragma unroll
        for (int fn = 0; fn < 2; fn++) {
            int col = col0 + warp_n * 16 + fn * 8 + 2 * tg;
            if (row < M) {
                float v0 = acc[fm][fn][0] + bias[col];
                float v1 = acc[fm][fn][1] + bias[col + 1];
                if (RELU) { v0 = fmaxf(v0, 0.f); v1 = fmaxf(v1, 0.f); }
                C[(size_t)row * N + col] = v0;
                C[(size_t)row * N + col + 1] = v1;
            }
            if (row + 8 < M) {
                float v2 = acc[fm][fn][2] + bias[col];
                float v3 = acc[fm][fn][3] + bias[col + 1];
                if (RELU) { v2 = fmaxf(v2, 0.f); v3 = fmaxf(v3, 0.f); }
                C[(size_t)(row + 8) * N + col] = v2;
                C[(size_t)(row + 8) * N + col + 1] = v3;
            }
        }
    }
}

// Zero-init first n floats
__global__ void zero_kernel(float* __restrict__ p, size_t n) {
    size_t i = (size_t)blockIdx.x * blockDim.x + threadIdx.x;
    size_t stride = (size_t)gridDim.x * blockDim.x;
    for (; i < n; i += stride) p[i] = 0.0f;
}

// Edge segment-max: neigh[dst] = max(neigh[dst], m[src]).
// m >= 0 (relu) -> int-bitpattern atomicMax == float max; zero floor correct.
__global__ __launch_bounds__(256)
void edge_max_kernel(const int* __restrict__ src,
                     const int* __restrict__ dst,
                     const float* __restrict__ m,
                     float* __restrict__ neigh, int d) {
    int e = blockIdx.x * 8 + (threadIdx.x >> 5);
    if (e >= N_EDGES) return;
    int lane = threadIdx.x & 31;
    int s = src[e];
    int t = dst[e];
    const float4* __restrict__ mrow = (const float4*)(m + (size_t)s * d);
    int* __restrict__ nrow = (int*)(neigh + (size_t)t * d);
    int d4 = d >> 2;
    for (int q = lane; q < d4; q += 32) {
        float4 v = mrow[q];
        int f = q * 4;
        atomicMax(nrow + f + 0, __float_as_int(v.x));
        atomicMax(nrow + f + 1, __float_as_int(v.y));
        atomicMax(nrow + f + 2, __float_as_int(v.z));
        atomicMax(nrow + f + 3, __float_as_int(v.w));
    }
}

// Final layer (d_out = 1): out[i] = sigmoid(dot(x,Ws2) + dot(neigh,Wn2) + b2)
__global__ __launch_bounds__(256)
void out_kernel(const float* __restrict__ x, const float* __restrict__ neigh,
                const float* __restrict__ Ws, const float* __restrict__ Wn,
                const float* __restrict__ b, float* __restrict__ out) {
    int warp = (blockIdx.x * blockDim.x + threadIdx.x) >> 5;
    int lane = threadIdx.x & 31;
    if (warp >= N_NODES) return;
    const float* __restrict__ xr = x + (size_t)warp * 512;
    const float* __restrict__ nr = neigh + (size_t)warp * 512;
    float s = 0.0f;
#pragma unroll 4
    for (int f = lane; f < 512; f += 32)
        s = fmaf(xr[f], Ws[f], fmaf(nr[f], Wn[f], s));
#pragma unroll
    for (int o = 16; o; o >>= 1) s += __shfl_xor_sync(0xFFFFFFFFu, s, o);
    if (lane == 0) out[warp] = 1.0f / (1.0f + expf(-(s + b[0])));
}

extern "C" void kernel_launch(void* const* d_in, const int* in_sizes, int n_in,
                              void* d_out, int out_size) {
    const float* h   = (const float*)d_in[0];
    const int*   src = (const int*)d_in[1];
    const int*   dst = (const int*)d_in[2];
    const float* Wp0 = (const float*)d_in[3];
    const float* bp0 = (const float*)d_in[4];
    const float* Ws0 = (const float*)d_in[5];
    const float* Wn0 = (const float*)d_in[6];
    const float* b0  = (const float*)d_in[7];
    const float* Wp1 = (const float*)d_in[8];
    const float* bp1 = (const float*)d_in[9];
    const float* Ws1 = (const float*)d_in[10];
    const float* Wn1 = (const float*)d_in[11];
    const float* b1  = (const float*)d_in[12];
    const float* Wp2 = (const float*)d_in[13];
    const float* bp2 = (const float*)d_in[14];
    const float* Ws2 = (const float*)d_in[15];
    const float* Wn2 = (const float*)d_in[16];
    const float* b2  = (const float*)d_in[17];
    float* out = (float*)d_out;

    float *m_buf, *neigh_buf, *x0_buf, *x1_buf;
    cudaGetSymbolAddress((void**)&m_buf, g_m);
    cudaGetSymbolAddress((void**)&neigh_buf, g_neigh);
    cudaGetSymbolAddress((void**)&x0_buf, g_x0);
    cudaGetSymbolAddress((void**)&x1_buf, g_x1);

    const int M = N_NODES;
    const int mtiles = (M + 127) / 128;
    const int eblocks = (N_EDGES + 7) / 8;

    // ---------------- Layer 0 (960 -> 512) ----------------
    gemm_tc<true, false><<<dim3(960 / 64, mtiles), 256>>>(
        h, Wp0, nullptr, nullptr, bp0, m_buf, M, 960, 960);
    zero_kernel<<<512, 256>>>(neigh_buf, (size_t)N_NODES * 960);
    edge_max_kernel<<<eblocks, 256>>>(src, dst, m_buf, neigh_buf, 960);
    gemm_tc<true, true><<<dim3(512 / 64, mtiles), 256>>>(
        h, Ws0, neigh_buf, Wn0, b0, x0_buf, M, 512, 960);

    // ---------------- Layer 1 (512 -> 512) ----------------
    gemm_tc<true, false><<<dim3(512 / 64, mtiles), 256>>>(
        x0_buf, Wp1, nullptr, nullptr, bp1, m_buf, M, 512, 512);
    zero_kernel<<<512, 256>>>(neigh_buf, (size_t)N_NODES * 512);
    edge_max_kernel<<<eblocks, 256>>>(src, dst, m_buf, neigh_buf, 512);
    gemm_tc<true, true><<<dim3(512 / 64, mtiles), 256>>>(
        x0_buf, Ws1, neigh_buf, Wn1, b1, x1_buf, M, 512, 512);

    // ---------------- Layer 2 (512 -> 1, sigmoid) ----------------
    gemm_tc<true, false><<<dim3(512 / 64, mtiles), 256>>>(
        x1_buf, Wp2, nullptr, nullptr, bp2, m_buf, M, 512, 512);
    zero_kernel<<<512, 256>>>(neigh_buf, (size_t)N_NODES * 512);
    edge_max_kernel<<<eblocks, 256>>>(src, dst, m_buf, neigh_buf, 512);
    out_kernel<<<(N_NODES * 32 + 255) / 256, 256>>>(
        x1_buf, neigh_buf, Ws2, Wn2, b2, out);
}

// round 9
// speedup vs baseline: 1.4334x; 1.3351x over previous
#include <cuda_runtime.h>
#include <cuda_bf16.h>
#include <cstdint>
#include <math.h>

// ResidueGCN: 3-layer GraphSAGE (pool aggregator)
// GEMMs on tensor cores: bf16 split (hi/lo) 3-product emulation of fp32,
// mma.sync.m16n8k16 + ldmatrix fragment loads.

#define N_NODES 10000
#define N_EDGES 160000

__device__ float g_m[N_NODES * 960];
__device__ float g_neigh[N_NODES * 960];
__device__ float g_x0[N_NODES * 512];
__device__ float g_x1[N_NODES * 512];

__device__ __forceinline__ unsigned pack_bf16(__nv_bfloat16 a, __nv_bfloat16 b) {
    return (unsigned)__bfloat16_as_ushort(a) | ((unsigned)__bfloat16_as_ushort(b) << 16);
}

// Split float4 into bf16 hi (rn) and bf16 lo (residual), packed pairs.
__device__ __forceinline__ void cvt_split4(float4 v, uint2& hi, uint2& lo) {
    __nv_bfloat16 h0 = __float2bfloat16_rn(v.x);
    __nv_bfloat16 h1 = __float2bfloat16_rn(v.y);
    __nv_bfloat16 h2 = __float2bfloat16_rn(v.z);
    __nv_bfloat16 h3 = __float2bfloat16_rn(v.w);
    __nv_bfloat16 l0 = __float2bfloat16_rn(v.x - __bfloat162float(h0));
    __nv_bfloat16 l1 = __float2bfloat16_rn(v.y - __bfloat162float(h1));
    __nv_bfloat16 l2 = __float2bfloat16_rn(v.z - __bfloat162float(h2));
    __nv_bfloat16 l3 = __float2bfloat16_rn(v.w - __bfloat162float(h3));
    hi = make_uint2(pack_bf16(h0, h1), pack_bf16(h2, h3));
    lo = make_uint2(pack_bf16(l0, l1), pack_bf16(l2, l3));
}

__device__ __forceinline__ void ldsm_x4(unsigned* r, unsigned addr) {
    asm volatile("ldmatrix.sync.aligned.m8n8.x4.shared.b16 {%0,%1,%2,%3}, [%4];"
                 : "=r"(r[0]), "=r"(r[1]), "=r"(r[2]), "=r"(r[3]) : "r"(addr));
}
__device__ __forceinline__ void ldsm_x2t(unsigned* r, unsigned addr) {
    asm volatile("ldmatrix.sync.aligned.m8n8.x2.trans.shared.b16 {%0,%1}, [%2];"
                 : "=r"(r[0]), "=r"(r[1]) : "r"(addr));
}

__device__ __forceinline__ void mma16(float* d, const unsigned* a, const unsigned* b) {
    asm volatile(
        "mma.sync.aligned.m16n8k16.row.col.f32.bf16.bf16.f32 "
        "{%0,%1,%2,%3}, {%4,%5,%6,%7}, {%8,%9}, {%0,%1,%2,%3};"
        : "+f"(d[0]), "+f"(d[1]), "+f"(d[2]), "+f"(d[3])
        : "r"(a[0]), "r"(a[1]), "r"(a[2]), "r"(a[3]), "r"(b[0]), "r"(b[1]));
}

// ---------------------------------------------------------------------------
// Tensor-core GEMM: C[M,N] = act( A1@B1 (+ A2@B2 if DUAL) + bias )
// BM=128, BN=64, BK=16, 256 threads (8 warps: 2 over M x 4 over N).
// Warp tile m64 x n16. bf16 hi/lo split, 3 products per fragment pair.
// A smem [m][k] stride 24 bf16; B smem [k][n] stride 72 bf16.
// All ldmatrix phases verified bank-conflict-free; frag addrs loop-invariant.
// Requires K % 16 == 0, N % 64 == 0 (holds: 960/512). M edge guarded.
// ---------------------------------------------------------------------------
template <bool RELU, bool DUAL>
__global__ __launch_bounds__(256, 2)
void gemm_tc(const float* __restrict__ A1, const float* __restrict__ B1,
             const float* __restrict__ A2, const float* __restrict__ B2,
             const float* __restrict__ bias, float* __restrict__ C,
             int M, int N, int K) {
    const int BM = 128, BK = 16;
    const int ASTR = 24;   // bf16 elems per A row (16 + 8 pad)
    const int BSTR = 72;   // bf16 elems per B row (64 + 8 pad)
    __shared__ __align__(16) unsigned short sAh[BM * ASTR], sAl[BM * ASTR];
    __shared__ __align__(16) unsigned short sBh[BK * BSTR], sBl[BK * BSTR];

    const int tid = threadIdx.x;
    const int lane = tid & 31, wid = tid >> 5;
    const int warp_m = wid & 1;
    const int warp_n = wid >> 1;
    const int row0 = blockIdx.y * BM;
    const int col0 = blockIdx.x * 64;
    const int g = lane >> 2;
    const int tg = lane & 3;

    // Staging geometry
    const int a_m0 = tid >> 2;          // 0..63
    const int a_m1 = a_m0 + 64;
    const int a_kq = (tid & 3) * 4;     // 0,4,8,12
    const int b_k = tid >> 4;           // 0..15
    const int b_n = (tid & 15) * 4;     // 0..60

    // ldmatrix addresses (loop-invariant)
    const unsigned baseAh = (unsigned)__cvta_generic_to_shared(sAh);
    const unsigned baseAl = (unsigned)__cvta_generic_to_shared(sAl);
    const unsigned baseBh = (unsigned)__cvta_generic_to_shared(sBh);
    const unsigned baseBl = (unsigned)__cvta_generic_to_shared(sBl);
    unsigned aoff[4], boff[2];
#pragma unroll
    for (int fm = 0; fm < 4; fm++)
        aoff[fm] = ((warp_m * 64 + fm * 16 + (lane & 15)) * ASTR + (lane >> 4) * 8) * 2;
#pragma unroll
    for (int fn = 0; fn < 2; fn++)
        boff[fn] = ((lane & 15) * BSTR + warp_n * 16 + fn * 8) * 2;

    float acc[4][2][4];
#pragma unroll
    for (int i = 0; i < 4; i++)
#pragma unroll
        for (int j = 0; j < 2; j++)
#pragma unroll
            for (int r = 0; r < 4; r++) acc[i][j][r] = 0.0f;

    const int npass = DUAL ? 2 : 1;
    for (int pass = 0; pass < npass; ++pass) {
        const float* __restrict__ A = (DUAL && pass) ? A2 : A1;
        const float* __restrict__ B = (DUAL && pass) ? B2 : B1;

        float4 ra0 = make_float4(0.f, 0.f, 0.f, 0.f);
        float4 ra1 = make_float4(0.f, 0.f, 0.f, 0.f);
        float4 rb;
        if (row0 + a_m0 < M)
            ra0 = *(const float4*)(A + (size_t)(row0 + a_m0) * K + a_kq);
        if (row0 + a_m1 < M)
            ra1 = *(const float4*)(A + (size_t)(row0 + a_m1) * K + a_kq);
        rb = *(const float4*)(B + (size_t)b_k * N + col0 + b_n);

        for (int k0 = 0; k0 < K; k0 += BK) {
            // Convert staged regs to bf16 hi/lo, commit to smem
            {
                uint2 hi, lo;
                cvt_split4(ra0, hi, lo);
                *(uint2*)(sAh + a_m0 * ASTR + a_kq) = hi;
                *(uint2*)(sAl + a_m0 * ASTR + a_kq) = lo;
                cvt_split4(ra1, hi, lo);
                *(uint2*)(sAh + a_m1 * ASTR + a_kq) = hi;
                *(uint2*)(sAl + a_m1 * ASTR + a_kq) = lo;
                cvt_split4(rb, hi, lo);
                *(uint2*)(sBh + b_k * BSTR + b_n) = hi;
                *(uint2*)(sBl + b_k * BSTR + b_n) = lo;
            }
            __syncthreads();

            // Stage next tile (overlaps with tensor work)
            int kn = k0 + BK;
            if (kn < K) {
                ra0 = make_float4(0.f, 0.f, 0.f, 0.f);
                ra1 = make_float4(0.f, 0.f, 0.f, 0.f);
                if (row0 + a_m0 < M)
                    ra0 = *(const float4*)(A + (size_t)(row0 + a_m0) * K + kn + a_kq);
                if (row0 + a_m1 < M)
                    ra1 = *(const float4*)(A + (size_t)(row0 + a_m1) * K + kn + a_kq);
                rb = *(const float4*)(B + (size_t)(kn + b_k) * N + col0 + b_n);
            }

            // Fragment loads (whole BK=16 slab per frag; addrs invariant)
            unsigned ah[4][4], al[4][4], bh[2][2], bl[2][2];
#pragma unroll
            for (int fm = 0; fm < 4; fm++) {
                ldsm_x4(ah[fm], baseAh + aoff[fm]);
                ldsm_x4(al[fm], baseAl + aoff[fm]);
            }
#pragma unroll
            for (int fn = 0; fn < 2; fn++) {
                ldsm_x2t(bh[fn], baseBh + boff[fn]);
                ldsm_x2t(bl[fn], baseBl + boff[fn]);
            }

#pragma unroll
            for (int fm = 0; fm < 4; fm++)
#pragma unroll
                for (int fn = 0; fn < 2; fn++) {
                    mma16(acc[fm][fn], ah[fm], bh[fn]);
                    mma16(acc[fm][fn], al[fm], bh[fn]);
                    mma16(acc[fm][fn], ah[fm], bl[fn]);
                }
            __syncthreads();
        }
    }

    // Epilogue: c0,c1 at (row, col+{0,1}); c2,c3 at (row+8, col+{0,1})
#pragma unroll
    for (int fm = 0; fm < 4; fm++) {
        int row = row0 + warp_m * 64 + fm * 16 + g;
#pragma unroll
        for (int fn = 0; fn < 2; fn++) {
            int col = col0 + warp_n * 16 + fn * 8 + 2 * tg;
            if (row < M) {
                float v0 = acc[fm][fn][0] + bias[col];
                float v1 = acc[fm][fn][1] + bias[col + 1];
                if (RELU) { v0 = fmaxf(v0, 0.f); v1 = fmaxf(v1, 0.f); }
                C[(size_t)row * N + col] = v0;
                C[(size_t)row * N + col + 1] = v1;
            }
            if (row + 8 < M) {
                float v2 = acc[fm][fn][2] + bias[col];
                float v3 = acc[fm][fn][3] + bias[col + 1];
                if (RELU) { v2 = fmaxf(v2, 0.f); v3 = fmaxf(v3, 0.f); }
                C[(size_t)(row + 8) * N + col] = v2;
                C[(size_t)(row + 8) * N + col + 1] = v3;
            }
        }
    }
}

// Zero-init first n floats
__global__ void zero_kernel(float* __restrict__ p, size_t n) {
    size_t i = (size_t)blockIdx.x * blockDim.x + threadIdx.x;
    size_t stride = (size_t)gridDim.x * blockDim.x;
    for (; i < n; i += stride) p[i] = 0.0f;
}

// Edge segment-max: neigh[dst] = max(neigh[dst], m[src]).
// m >= 0 (relu) -> int-bitpattern atomicMax == float max; zero floor correct.
__global__ __launch_bounds__(256)
void edge_max_kernel(const int* __restrict__ src,
                     const int* __restrict__ dst,
                     const float* __restrict__ m,
                     float* __restrict__ neigh, int d) {
    int e = blockIdx.x * 8 + (threadIdx.x >> 5);
    if (e >= N_EDGES) return;
    int lane = threadIdx.x & 31;
    int s = src[e];
    int t = dst[e];
    const float4* __restrict__ mrow = (const float4*)(m + (size_t)s * d);
    int* __restrict__ nrow = (int*)(neigh + (size_t)t * d);
    int d4 = d >> 2;
    for (int q = lane; q < d4; q += 32) {
        float4 v = mrow[q];
        int f = q * 4;
        atomicMax(nrow + f + 0, __float_as_int(v.x));
        atomicMax(nrow + f + 1, __float_as_int(v.y));
        atomicMax(nrow + f + 2, __float_as_int(v.z));
        atomicMax(nrow + f + 3, __float_as_int(v.w));
    }
}

// Final layer (d_out = 1): out[i] = sigmoid(dot(x,Ws2) + dot(neigh,Wn2) + b2)
__global__ __launch_bounds__(256)
void out_kernel(const float* __restrict__ x, const float* __restrict__ neigh,
                const float* __restrict__ Ws, const float* __restrict__ Wn,
                const float* __restrict__ b, float* __restrict__ out) {
    int warp = (blockIdx.x * blockDim.x + threadIdx.x) >> 5;
    int lane = threadIdx.x & 31;
    if (warp >= N_NODES) return;
    const float* __restrict__ xr = x + (size_t)warp * 512;
    const float* __restrict__ nr = neigh + (size_t)warp * 512;
    float s = 0.0f;
#pragma unroll 4
    for (int f = lane; f < 512; f += 32)
        s = fmaf(xr[f], Ws[f], fmaf(nr[f], Wn[f], s));
#pragma unroll
    for (int o = 16; o; o >>= 1) s += __shfl_xor_sync(0xFFFFFFFFu, s, o);
    if (lane == 0) out[warp] = 1.0f / (1.0f + expf(-(s + b[0])));
}

extern "C" void kernel_launch(void* const* d_in, const int* in_sizes, int n_in,
                              void* d_out, int out_size) {
    const float* h   = (const float*)d_in[0];
    const int*   src = (const int*)d_in[1];
    const int*   dst = (const int*)d_in[2];
    const float* Wp0 = (const float*)d_in[3];
    const float* bp0 = (const float*)d_in[4];
    const float* Ws0 = (const float*)d_in[5];
    const float* Wn0 = (const float*)d_in[6];
    const float* b0  = (const float*)d_in[7];
    const float* Wp1 = (const float*)d_in[8];
    const float* bp1 = (const float*)d_in[9];
    const float* Ws1 = (const float*)d_in[10];
    const float* Wn1 = (const float*)d_in[11];
    const float* b1  = (const float*)d_in[12];
    const float* Wp2 = (const float*)d_in[13];
    const float* bp2 = (const float*)d_in[14];
    const float* Ws2 = (const float*)d_in[15];
    const float* Wn2 = (const float*)d_in[16];
    const float* b2  = (const float*)d_in[17];
    float* out = (float*)d_out;

    float *m_buf, *neigh_buf, *x0_buf, *x1_buf;
    cudaGetSymbolAddress((void**)&m_buf, g_m);
    cudaGetSymbolAddress((void**)&neigh_buf, g_neigh);
    cudaGetSymbolAddress((void**)&x0_buf, g_x0);
    cudaGetSymbolAddress((void**)&x1_buf, g_x1);

    const int M = N_NODES;
    const int mtiles = (M + 127) / 128;
    const int eblocks = (N_EDGES + 7) / 8;

    // ---------------- Layer 0 (960 -> 512) ----------------
    gemm_tc<true, false><<<dim3(960 / 64, mtiles), 256>>>(
        h, Wp0, nullptr, nullptr, bp0, m_buf, M, 960, 960);
    zero_kernel<<<512, 256>>>(neigh_buf, (size_t)N_NODES * 960);
    edge_max_kernel<<<eblocks, 256>>>(src, dst, m_buf, neigh_buf, 960);
    gemm_tc<true, true><<<dim3(512 / 64, mtiles), 256>>>(
        h, Ws0, neigh_buf, Wn0, b0, x0_buf, M, 512, 960);

    // ---------------- Layer 1 (512 -> 512) ----------------
    gemm_tc<true, false><<<dim3(512 / 64, mtiles), 256>>>(
        x0_buf, Wp1, nullptr, nullptr, bp1, m_buf, M, 512, 512);
    zero_kernel<<<512, 256>>>(neigh_buf, (size_t)N_NODES * 512);
    edge_max_kernel<<<eblocks, 256>>>(src, dst, m_buf, neigh_buf, 512);
    gemm_tc<true, true><<<dim3(512 / 64, mtiles), 256>>>(
        x0_buf, Ws1, neigh_buf, Wn1, b1, x1_buf, M, 512, 512);

    // ---------------- Layer 2 (512 -> 1, sigmoid) ----------------
    gemm_tc<true, false><<<dim3(512 / 64, mtiles), 256>>>(
        x1_buf, Wp2, nullptr, nullptr, bp2, m_buf, M, 512, 512);
    zero_kernel<<<512, 256>>>(neigh_buf, (size_t)N_NODES * 512);
    edge_max_kernel<<<eblocks, 256>>>(src, dst, m_buf, neigh_buf, 512);
    out_kernel<<<(N_NODES * 32 + 255) / 256, 256>>>(
        x1_buf, neigh_buf, Ws2, Wn2, b2, out);
}